// round 6
// baseline (speedup 1.0000x reference)
#include <cuda_runtime.h>
#include <cuda_bf16.h>

// video [B=8, C=3, T=32, H=224, W=224] fp32.
// out[b,c,t,y,x] = clip01( clamped-bilinear sample of frame (b,c,t) at
//   src = (coord + shake + 0.5) * (224/240) - 0.5 )
// (trilinear resize 224->240 has identity T axis; jax boundary weight
//  renormalization for the linear kernel == coordinate clamping.)
//
// R5: barrier-free register-rolling column walk.
// Thread = one x column; scale 14/15 < 1 makes y->source-row monotone with
// step <= 1, so the two horizontally-lerped source rows live in registers.
// Block processes 2 planes sharing the same t (identical weights) -> index
// math amortized 2x, 4 independent LDGs per row advance (MLP 4).
// No smem, no __syncthreads.

#define HH 224
#define WW 224
#define TT 32
#define PLANE_SZ (HH * WW)
#define SEGROWS 32
#define NSEG (HH / SEGROWS)      // 7
#define NPAIR 12                 // 24 bc-planes / 2
#define SCALE_F (14.0f / 15.0f)

__global__ __launch_bounds__(224) void shake_colwalk_kernel(
    const float* __restrict__ vid,
    const int*   __restrict__ sh,
    const int*   __restrict__ sw,
    float*       __restrict__ out)
{
    int blk = blockIdx.x;
    int seg = blk % NSEG;
    int g   = (blk / NSEG) % NPAIR;
    int t   = blk / (NSEG * NPAIR);      // 0..31

    int sht = __ldg(sh + t);
    int swt = __ldg(sw + t);
    int ys  = seg * SEGROWS;
    int x   = threadIdx.x;               // 0..223

    // Two planes sharing this t: plane = bc*TT + t
    long long p0 = (long long)(2 * g)     * TT + t;
    long long p1 = (long long)(2 * g + 1) * TT + t;
    const float* pl0 = vid + p0 * PLANE_SZ;
    const float* pl1 = vid + p1 * PLANE_SZ;
    float* o0 = out + p0 * PLANE_SZ + x;
    float* o1 = out + p1 * PLANE_SZ + x;

    // Horizontal weights (fixed per thread for the whole segment)
    float sx  = ((float)(x + swt) + 0.5f) * SCALE_F - 0.5f;
    float fx0 = floorf(sx);
    float fx  = sx - fx0;
    int   xi  = (int)fx0;
    int   x0c = max(xi, 0);
    int   x1c = min(xi + 1, WW - 1);

    // Preload the first two (clamped) source rows for both planes.
    float syf = ((float)(ys + sht) + 0.5f) * SCALE_F - 0.5f;
    int   rlo = (int)floorf(syf);        // may be -1 at the very top

    int rc0 = min(max(rlo, 0), HH - 1);
    int rc1 = min(max(rlo + 1, 0), HH - 1);

    const float* ra0 = pl0 + rc0 * WW;
    const float* rb0 = pl1 + rc0 * WW;
    const float* ra1 = pl0 + rc1 * WW;
    const float* rb1 = pl1 + rc1 * WW;

    float a00 = __ldg(ra0 + x0c), a01 = __ldg(ra0 + x1c);
    float b00 = __ldg(rb0 + x0c), b01 = __ldg(rb0 + x1c);
    float a10 = __ldg(ra1 + x0c), a11 = __ldg(ra1 + x1c);
    float b10 = __ldg(rb1 + x0c), b11 = __ldg(rb1 + x1c);

    float hA0 = fmaf(fx, a01 - a00, a00);   // plane0, row rlo
    float hB0 = fmaf(fx, b01 - b00, b00);   // plane1, row rlo
    float hA1 = fmaf(fx, a11 - a10, a10);   // plane0, row rlo+1
    float hB1 = fmaf(fx, b11 - b10, b10);   // plane1, row rlo+1

#pragma unroll 4
    for (int y = 0; y < SEGROWS; y++) {
        float sy = ((float)(ys + y + sht) + 0.5f) * SCALE_F - 0.5f;
        float f0 = floorf(sy);
        int   r  = (int)f0;
        float fy = sy - f0;

        if (r > rlo) {                    // uniform across the block
            rlo = r;
            int rc = min(r + 1, HH - 1);  // r+1 >= 0 always here
            const float* ra = pl0 + rc * WW;
            const float* rb = pl1 + rc * WW;
            float na0 = __ldg(ra + x0c), na1 = __ldg(ra + x1c);
            float nb0 = __ldg(rb + x0c), nb1 = __ldg(rb + x1c);
            hA0 = hA1;
            hB0 = hB1;
            hA1 = fmaf(fx, na1 - na0, na0);
            hB1 = fmaf(fx, nb1 - nb0, nb0);
        }

        float vA = fmaf(fy, hA1 - hA0, hA0);
        float vB = fmaf(fy, hB1 - hB0, hB0);
        vA = fminf(fmaxf(vA, 0.0f), 1.0f);
        vB = fminf(fmaxf(vB, 0.0f), 1.0f);

        int off = (ys + y) * WW;
        o0[off] = vA;
        o1[off] = vB;
    }
}

extern "C" void kernel_launch(void* const* d_in, const int* in_sizes, int n_in,
                              void* d_out, int out_size)
{
    const float* vid = (const float*)d_in[0];
    const int*   sh  = (const int*)d_in[1];
    const int*   sw  = (const int*)d_in[2];
    float*       out = (float*)d_out;

    int blocks = TT * NPAIR * NSEG;      // 32*12*7 = 2688
    shake_colwalk_kernel<<<blocks, 224>>>(vid, sh, sw, out);
}

// round 7
// speedup vs baseline: 1.0697x; 1.0697x over previous
#include <cuda_runtime.h>
#include <cuda_bf16.h>

// video [B=8, C=3, T=32, H=224, W=224] fp32.
// out[b,c,t,y,x] = clip01( clamped-bilinear sample of frame (b,c,t) at
//   src = (coord + shake + 0.5) * (224/240) - 0.5 )
// (trilinear resize 224->240 has identity T axis; jax boundary weight
//  renormalization for the linear kernel == coordinate clamping.)
//
// R6: single-stage smem pipeline (R4 minus one barrier + half the smem).
//  Fused A+B: horizontal lerp directly from global -> hrow
//             (2 near-coalesced scalar LDGs per (row, x); 32 independent
//              loads per thread -> high MLP)
//  C: vertical lerp via two ALIGNED float4 LDS + float4 STG.
// smem 14.3 KB -> 9 blocks/SM (98% occ), ONE __syncthreads per tile.

#define HH 224
#define WW 224
#define TT 32
#define NPLANES 768                     // B*C*T
#define TILE_Y 16
#define TILES_PER_PLANE (HH / TILE_Y)   // 14
#define THREADS 224
#define SCALE_F (14.0f / 15.0f)

__global__ __launch_bounds__(THREADS) void shake_bilinear_fused_kernel(
    const float* __restrict__ vid,
    const int*   __restrict__ sh,
    const int*   __restrict__ sw,
    float*       __restrict__ out)
{
    __shared__ float hrow[TILE_Y][WW];   // 14336 B

    int blk  = blockIdx.x;
    int tile = blk % TILES_PER_PLANE;
    int p    = blk / TILES_PER_PLANE;    // plane = (b*C + c)*T + t
    int t    = p & (TT - 1);
    int sht  = __ldg(sh + t);
    int swt  = __ldg(sw + t);
    int yb   = tile * TILE_Y;
    int tid  = threadIdx.x;

    // Base source row for this tile (may be -1 at the top edge).
    float sy0  = ((float)(yb + sht) + 0.5f) * SCALE_F - 0.5f;
    int   base = (int)floorf(sy0);

    const float* plane = vid + (long long)p * (HH * WW);

    // ---- Fused Stage A+B: horizontal lerp straight from global ----
    {
        int   x   = tid;                 // 0..223
        float sx  = ((float)(x + swt) + 0.5f) * SCALE_F - 0.5f;
        float f0  = floorf(sx);
        float fx  = sx - f0;
        int   x0  = (int)f0;
        int   x0c = max(x0, 0);
        int   x1c = min(x0 + 1, WW - 1);
#pragma unroll
        for (int r = 0; r < TILE_Y; r++) {
            int srcr = min(max(base + r, 0), HH - 1);
            const float* row = plane + srcr * WW;
            float s0 = __ldg(row + x0c);
            float s1 = __ldg(row + x1c);
            hrow[r][x] = fmaf(fx, s1 - s0, s0);
        }
    }
    __syncthreads();

    // ---- Stage C: vertical lerp, aligned float4 LDS x2 per quad ----
    int x4 = tid % (WW / 4);             // 0..55
    int yy = tid / (WW / 4);             // 0..3
    int xb = x4 * 4;

    float4* outp = (float4*)(out + (long long)p * (HH * WW));
#pragma unroll
    for (int k = 0; k < 4; k++) {
        int   y   = yy + 4 * k;          // 0..15
        float sy  = ((float)(yb + y + sht) + 0.5f) * SCALE_F - 0.5f;
        float f0  = floorf(sy);
        float fy  = sy - f0;
        int   r0  = (int)f0 - base;      // in [0,14]; r0+1 <= 15 (clamped rows)

        float4 a = *(const float4*)(&hrow[r0][xb]);
        float4 b = *(const float4*)(&hrow[r0 + 1][xb]);

        float4 res;
        res.x = fminf(fmaxf(fmaf(fy, b.x - a.x, a.x), 0.0f), 1.0f);
        res.y = fminf(fmaxf(fmaf(fy, b.y - a.y, a.y), 0.0f), 1.0f);
        res.z = fminf(fmaxf(fmaf(fy, b.z - a.z, a.z), 0.0f), 1.0f);
        res.w = fminf(fmaxf(fmaf(fy, b.w - a.w, a.w), 0.0f), 1.0f);

        outp[(yb + y) * (WW / 4) + x4] = res;
    }
}

extern "C" void kernel_launch(void* const* d_in, const int* in_sizes, int n_in,
                              void* d_out, int out_size)
{
    const float* vid = (const float*)d_in[0];
    const int*   sh  = (const int*)d_in[1];
    const int*   sw  = (const int*)d_in[2];
    float*       out = (float*)d_out;

    int blocks = NPLANES * TILES_PER_PLANE; // 10752
    shake_bilinear_fused_kernel<<<blocks, THREADS>>>(vid, sh, sw, out);
}